// round 7
// baseline (speedup 1.0000x reference)
#include <cuda_runtime.h>
#include <cuda_fp16.h>
#include <cstdint>

#define TPB 256
#define RPB 64
#define PAD 136    // fp16 elems per k-row of A2/W2 tiles (272B stride, conflict-free)
#define HPAD 72    // fp16 elems per row of h2/W4 tiles (144B stride, conflict-free)

// ---------------- pre-split fp16 weights in device globals ----------------
// W2: 8 chunks of [64 n][136 k] fp16 (transposed: entry = W2[k][c*64+n])
__device__ __align__(16) unsigned char gW2h[8 * 17408];
__device__ __align__(16) unsigned char gW2l[8 * 17408];
// W4: 8 chunks of [40 n][72 k] fp16 (entry = W4[c*64+k][n])
__device__ __align__(16) unsigned char gW4h[8 * 5760];
__device__ __align__(16) unsigned char gW4l[8 * 5760];

__device__ __forceinline__ void split2h(float v, __half& h, __half& l) {
    h = __float2half_rn(v);
    l = __float2half_rn(v - __half2float(h));
}

__global__ void prep_kernel(const float* __restrict__ W2,
                            const float* __restrict__ W4) {
    int idx = blockIdx.x * blockDim.x + threadIdx.x;
    if (idx < 65536) {                    // W2 split: c(8) x n(64) x k(128)
        int c = idx >> 13, rem = idx & 8191;
        int n = rem >> 7, k = rem & 127;
        float v = W2[k * 512 + c * 64 + n];
        __half h, l; split2h(v, h, l);
        uint32_t off = (uint32_t)c * 17408u + (uint32_t)(n * PAD + k) * 2u;
        *(__half*)(gW2h + off) = h;
        *(__half*)(gW2l + off) = l;
    } else if (idx < 65536 + 20480) {     // W4 split: c(8) x n(40) x k(64), 2560/chunk
        int i = idx - 65536;
        int c = i / 2560, rem = i % 2560;
        int n = rem / 64, k = rem % 64;
        float v = W4[(c * 64 + k) * 40 + n];
        __half h, l; split2h(v, h, l);
        uint32_t off = (uint32_t)c * 5760u + (uint32_t)(n * HPAD + k) * 2u;
        *(__half*)(gW4h + off) = h;
        *(__half*)(gW4l + off) = l;
    }
}

// ---------------- PTX helpers ----------------
__device__ __forceinline__ uint32_t smem_u32(const void* p) {
    uint32_t a;
    asm("{ .reg .u64 t; cvta.to.shared.u64 t, %1; cvt.u32.u64 %0, t; }"
        : "=r"(a) : "l"(p));
    return a;
}
__device__ __forceinline__ void ldsm_x4(uint32_t* r, uint32_t addr) {
    asm volatile("ldmatrix.sync.aligned.m8n8.x4.shared.b16 {%0,%1,%2,%3}, [%4];"
        : "=r"(r[0]), "=r"(r[1]), "=r"(r[2]), "=r"(r[3]) : "r"(addr));
}
__device__ __forceinline__ void ldsm_x2(uint32_t* r, uint32_t addr) {
    asm volatile("ldmatrix.sync.aligned.m8n8.x2.shared.b16 {%0,%1}, [%2];"
        : "=r"(r[0]), "=r"(r[1]) : "r"(addr));
}
__device__ __forceinline__ void mma16816(float* d, const uint32_t* a, const uint32_t* b) {
    asm volatile("mma.sync.aligned.m16n8k16.row.col.f32.f16.f16.f32 "
        "{%0,%1,%2,%3}, {%4,%5,%6,%7}, {%8,%9}, {%0,%1,%2,%3};"
        : "+f"(d[0]), "+f"(d[1]), "+f"(d[2]), "+f"(d[3])
        : "r"(a[0]), "r"(a[1]), "r"(a[2]), "r"(a[3]), "r"(b[0]), "r"(b[1]));
}

// ---------------- smem layout (bytes) ----------------
#define S_A2H  0                       // h1 hi [64][PAD] f16 = 17408
#define S_A2L  17408                   // h1 lo
#define S_B    34816                   // W2 chunk hi / h2 hi [64][HPAD] / layer1 staging
#define S_BL   52224                   // W2 chunk lo / h2 lo
#define S_W4H  69632                   // W4 chunk hi [40][HPAD] = 5760
#define S_W4L  75392
#define S_BIAS 81152                   // b1(128) b2(512) b4(40) f32 = 2720
#define SMEM_BYTES 83872

__global__ __launch_bounds__(TPB, 2)
void dqn_hmma_kernel(const float* __restrict__ x,
                     const float* __restrict__ W1,
                     const float* __restrict__ b1,
                     const float* __restrict__ b2,
                     const float* __restrict__ b4,
                     float* __restrict__ out) {
    extern __shared__ char smem[];
    const uint32_t sb = smem_u32(smem);
    const int t    = threadIdx.x;
    const int wid  = t >> 5;
    const int lane = t & 31;
    const int blk  = blockIdx.x;

    float* b1s = (float*)(smem + S_BIAS);
    float* b2s = b1s + 128;
    float* b4s = b2s + 512;

    // ---------------- stage biases + layer1 inputs (staging aliases S_B) ----
    {
        float* xs  = (float*)(smem + S_B);    // 64*15 = 960 f32
        float* W1p = xs + 960;                // 36*128 = 4608 f32
        const float* xg = x + (size_t)blk * (RPB * 15);
        #pragma unroll
        for (int i = 0; i < 4; i++) {
            int idx = i * TPB + t;
            if (idx < 960) xs[idx] = xg[idx];
        }
        #pragma unroll
        for (int i = 0; i < 18; i++) W1p[i * TPB + t] = W1[i * TPB + t];
        if (t < 128) b1s[t] = b1[t];
        #pragma unroll
        for (int i = 0; i < 2; i++) b2s[i * TPB + t] = b2[i * TPB + t];
        if (t < 40) b4s[t] = b4[t];
        __syncthreads();

        // ---------------- layer 1 (fp32 exact) -> split-fp16 A2 tile --------
        // 256 threads: each covers one row's 32-col quarter.
        const int r  = t & 63;
        const int ch = t >> 6;                // 0..3
        const float* xr = xs + r * 15;
        float keep[11];
        #pragma unroll
        for (int k = 0; k < 11; k++) keep[k] = xr[k];
        int hh = (int)xr[11];      hh = hh < 0 ? 0 : (hh > 3 ? 3 : hh);
        int n0 = (int)xr[12] - 1;  n0 = n0 < 0 ? 0 : (n0 > 6 ? 6 : n0);
        int n1 = (int)xr[13] - 1;  n1 = n1 < 0 ? 0 : (n1 > 6 ? 6 : n1);
        int n2 = (int)xr[14] - 1;  n2 = n2 < 0 ? 0 : (n2 > 6 ? 6 : n2);
        const float* hrow = W1p + (11 + hh) * 128;
        const float* g0   = W1p + (15 + n0) * 128;
        const float* g1   = W1p + (22 + n1) * 128;
        const float* g2   = W1p + (29 + n2) * 128;

        #pragma unroll
        for (int c4 = 0; c4 < 8; c4++) {
            const int c = ch * 32 + c4 * 4;
            float4 acc = *(const float4*)(b1s + c);
            #pragma unroll
            for (int k = 0; k < 11; k++) {
                float4 w = *(const float4*)(W1p + k * 128 + c);
                acc.x += keep[k] * w.x; acc.y += keep[k] * w.y;
                acc.z += keep[k] * w.z; acc.w += keep[k] * w.w;
            }
            float4 wh = *(const float4*)(hrow + c);
            float4 w0 = *(const float4*)(g0 + c);
            float4 w1 = *(const float4*)(g1 + c);
            float4 w2 = *(const float4*)(g2 + c);
            acc.x = fmaxf(acc.x + wh.x + w0.x + w1.x + w2.x, 0.f);
            acc.y = fmaxf(acc.y + wh.y + w0.y + w1.y + w2.y, 0.f);
            acc.z = fmaxf(acc.z + wh.z + w0.z + w1.z + w2.z, 0.f);
            acc.w = fmaxf(acc.w + wh.w + w0.w + w1.w + w2.w, 0.f);
            __half hx, lx, hy, ly, hz, lz, hw, lw;
            split2h(acc.x, hx, lx); split2h(acc.y, hy, ly);
            split2h(acc.z, hz, lz); split2h(acc.w, hw, lw);
            uint32_t off = (uint32_t)(r * PAD + c) * 2u;
            *(__half2*)(smem + S_A2H + off)     = __halves2half2(hx, hy);
            *(__half2*)(smem + S_A2H + off + 4) = __halves2half2(hz, hw);
            *(__half2*)(smem + S_A2L + off)     = __halves2half2(lx, ly);
            *(__half2*)(smem + S_A2L + off + 4) = __halves2half2(lz, lw);
        }
    }
    __syncthreads();

    // ---------------- fragment lane mappings ----------------
    const int lr = lane & 15;              // ldmatrix A row offset
    const int lc = (lane >> 4) << 3;       // ldmatrix A col offset
    const int br = lane & 7;               // ldmatrix B row offset
    const int bc = ((lane >> 3) & 1) << 3; // ldmatrix B col offset
    const int gid = lane >> 2;
    const int tig = lane & 3;

    const int mi  = wid & 1;               // layer2 M32 block
    const int ni  = wid >> 1;              // layer2 N16 block (0..3)
    const int mi3 = wid & 1;               // layer3 M32 block
    const int kh3 = wid >> 1;              // layer3 K16 quarter (0..3)

    float o3[2][5][4];
    #pragma unroll
    for (int a = 0; a < 2; a++)
        #pragma unroll
        for (int b = 0; b < 5; b++)
            #pragma unroll
            for (int d = 0; d < 4; d++) o3[a][b][d] = 0.f;

    // ---------------- chunk loop: 8 x 64 j-cols ----------------
    for (int c = 0; c < 8; c++) {
        // copy W2 chunk (split) + W4 chunk (split)
        {
            const uint4* s1 = (const uint4*)(gW2h + (size_t)c * 17408);
            const uint4* s2 = (const uint4*)(gW2l + (size_t)c * 17408);
            uint4* d1 = (uint4*)(smem + S_B);
            uint4* d2 = (uint4*)(smem + S_BL);
            #pragma unroll
            for (int i = 0; i < 5; i++) {
                int idx = i * TPB + t;
                if (idx < 1088) { d1[idx] = s1[idx]; d2[idx] = s2[idx]; }
            }
            const uint4* s3 = (const uint4*)(gW4h + (size_t)c * 5760);
            const uint4* s4 = (const uint4*)(gW4l + (size_t)c * 5760);
            uint4* d3 = (uint4*)(smem + S_W4H);
            uint4* d4 = (uint4*)(smem + S_W4L);
            #pragma unroll
            for (int i = 0; i < 2; i++) {
                int idx = i * TPB + t;
                if (idx < 360) { d3[idx] = s3[idx]; d4[idx] = s4[idx]; }
            }
        }
        __syncthreads();

        // ---- layer2: warp 32x16 tile, K=128, 3-term split ----
        float acc[2][2][4];
        #pragma unroll
        for (int a = 0; a < 2; a++)
            #pragma unroll
            for (int b = 0; b < 2; b++)
                #pragma unroll
                for (int d = 0; d < 4; d++) acc[a][b][d] = 0.f;

        #pragma unroll
        for (int kt = 0; kt < 8; kt++) {
            const int k0 = kt * 16;
            uint32_t ah[2][4], al[2][4];
            #pragma unroll
            for (int mt = 0; mt < 2; mt++) {
                int row0 = mi * 32 + mt * 16;
                uint32_t off = (uint32_t)((row0 + lr) * PAD + k0 + lc) * 2u;
                ldsm_x4(ah[mt], sb + S_A2H + off);
                ldsm_x4(al[mt], sb + S_A2L + off);
            }
            uint32_t bh[2][2], bl[2][2];
            #pragma unroll
            for (int nt = 0; nt < 2; nt++) {
                int nrow = ni * 16 + nt * 8;
                uint32_t off = (uint32_t)((nrow + br) * PAD + k0 + bc) * 2u;
                ldsm_x2(bh[nt], sb + S_B + off);
                ldsm_x2(bl[nt], sb + S_BL + off);
            }
            #pragma unroll
            for (int mt = 0; mt < 2; mt++)
                #pragma unroll
                for (int nt = 0; nt < 2; nt++) {
                    mma16816(acc[mt][nt], ah[mt], bh[nt]);
                    mma16816(acc[mt][nt], ah[mt], bl[nt]);
                    mma16816(acc[mt][nt], al[mt], bh[nt]);
                }
        }
        __syncthreads();   // all warps done reading W2 chunk

        // ---- epilogue: +b2, relu, split-fp16 -> h2 tile (aliases W2 buf) ----
        #pragma unroll
        for (int mt = 0; mt < 2; mt++)
            #pragma unroll
            for (int nt = 0; nt < 2; nt++) {
                int j = ni * 16 + nt * 8 + 2 * tig;
                float bj0 = b2s[c * 64 + j], bj1 = b2s[c * 64 + j + 1];
                int row0 = mi * 32 + mt * 16 + gid;
                int row1 = row0 + 8;
                float v0 = fmaxf(acc[mt][nt][0] + bj0, 0.f);
                float v1 = fmaxf(acc[mt][nt][1] + bj1, 0.f);
                float v2 = fmaxf(acc[mt][nt][2] + bj0, 0.f);
                float v3 = fmaxf(acc[mt][nt][3] + bj1, 0.f);
                __half h0, l0, h1, l1, h2v, l2, h3, l3;
                split2h(v0, h0, l0); split2h(v1, h1, l1);
                split2h(v2, h2v, l2); split2h(v3, h3, l3);
                uint32_t o0 = (uint32_t)(row0 * HPAD + j) * 2u;
                uint32_t o1 = (uint32_t)(row1 * HPAD + j) * 2u;
                *(__half2*)(smem + S_B  + o0) = __halves2half2(h0, h1);
                *(__half2*)(smem + S_BL + o0) = __halves2half2(l0, l1);
                *(__half2*)(smem + S_B  + o1) = __halves2half2(h2v, h3);
                *(__half2*)(smem + S_BL + o1) = __halves2half2(l2, l3);
            }
        __syncthreads();

        // ---- layer3 partial: h2 chunk (K=64) x W4 chunk, K split 4-way ----
        {
            const int k0 = kh3 * 16;
            uint32_t ah[2][4], al[2][4];
            #pragma unroll
            for (int mt = 0; mt < 2; mt++) {
                int row0 = mi3 * 32 + mt * 16;
                uint32_t off = (uint32_t)((row0 + lr) * HPAD + k0 + lc) * 2u;
                ldsm_x4(ah[mt], sb + S_B + off);
                ldsm_x4(al[mt], sb + S_BL + off);
            }
            uint32_t bh[5][2], bl[5][2];
            #pragma unroll
            for (int nt = 0; nt < 5; nt++) {
                uint32_t off = (uint32_t)((nt * 8 + br) * HPAD + k0 + bc) * 2u;
                ldsm_x2(bh[nt], sb + S_W4H + off);
                ldsm_x2(bl[nt], sb + S_W4L + off);
            }
            #pragma unroll
            for (int mt = 0; mt < 2; mt++)
                #pragma unroll
                for (int nt = 0; nt < 5; nt++) {
                    mma16816(o3[mt][nt], ah[mt], bh[nt]);
                    mma16816(o3[mt][nt], ah[mt], bl[nt]);
                    mma16816(o3[mt][nt], al[mt], bh[nt]);
                }
        }
        __syncthreads();   // h2/W4 reads done before next chunk copy
    }

    // ---------------- cross-warp K reduction (4-way) + output ----------------
    float* sred = (float*)smem;   // aliases A2 region: 3 buffers x 64*40 f32 = 30720B
    if (kh3 != 0) {
        float* dst = sred + (kh3 - 1) * 2560;
        #pragma unroll
        for (int mt = 0; mt < 2; mt++)
            #pragma unroll
            for (int nt = 0; nt < 5; nt++) {
                int j = nt * 8 + 2 * tig;
                int r0 = mi3 * 32 + mt * 16 + gid;
                int r1 = r0 + 8;
                dst[r0 * 40 + j]     = o3[mt][nt][0];
                dst[r0 * 40 + j + 1] = o3[mt][nt][1];
                dst[r1 * 40 + j]     = o3[mt][nt][2];
                dst[r1 * 40 + j + 1] = o3[mt][nt][3];
            }
    }
    __syncthreads();
    if (kh3 == 0) {
        #pragma unroll
        for (int mt = 0; mt < 2; mt++)
            #pragma unroll
            for (int nt = 0; nt < 5; nt++) {
                int j = nt * 8 + 2 * tig;
                int r0 = mi3 * 32 + mt * 16 + gid;
                int r1 = r0 + 8;
                float s0 = o3[mt][nt][0] + b4s[j];
                float s1 = o3[mt][nt][1] + b4s[j + 1];
                float s2 = o3[mt][nt][2] + b4s[j];
                float s3 = o3[mt][nt][3] + b4s[j + 1];
                #pragma unroll
                for (int p = 0; p < 3; p++) {
                    const float* src = sred + p * 2560;
                    s0 += src[r0 * 40 + j];
                    s1 += src[r0 * 40 + j + 1];
                    s2 += src[r1 * 40 + j];
                    s3 += src[r1 * 40 + j + 1];
                }
                *(float2*)(out + ((size_t)blk * RPB + r0) * 40 + j) = make_float2(s0, s1);
                *(float2*)(out + ((size_t)blk * RPB + r1) * 40 + j) = make_float2(s2, s3);
            }
    }
}

extern "C" void kernel_launch(void* const* d_in, const int* in_sizes, int n_in,
                              void* d_out, int out_size) {
    const float* x  = (const float*)d_in[0];
    const float* W1 = (const float*)d_in[1];
    const float* b1 = (const float*)d_in[2];
    const float* W2 = (const float*)d_in[3];
    const float* b2 = (const float*)d_in[4];
    const float* W4 = (const float*)d_in[5];
    const float* b4 = (const float*)d_in[6];
    float* out = (float*)d_out;

    prep_kernel<<<336, 256>>>(W2, W4);

    const int B = in_sizes[0] / 15;      // 131072
    const int grid = B / RPB;            // 2048
    cudaFuncSetAttribute(dqn_hmma_kernel,
                         cudaFuncAttributeMaxDynamicSharedMemorySize, SMEM_BYTES);
    dqn_hmma_kernel<<<grid, TPB, SMEM_BYTES>>>(x, W1, b1, b2, b4, out);
}

// round 8
// speedup vs baseline: 1.3461x; 1.3461x over previous
#include <cuda_runtime.h>
#include <cuda_fp16.h>
#include <cstdint>

#define TPB 128
#define RPB 64
#define PAD 136    // fp16 elems per k-row of A2/W2 tiles (272B stride, conflict-free)
#define HPAD 72    // fp16 elems per row of h2/W4 tiles (144B stride, conflict-free)

// ---------------- pre-split fp16 weights in device globals ----------------
// W2: 8 chunks of [64 n][136 k] fp16 (transposed: entry = W2[k][c*64+n])
__device__ __align__(16) unsigned char gW2h[8 * 17408];
__device__ __align__(16) unsigned char gW2l[8 * 17408];
// W4: 8 chunks of [40 n][72 k] fp16 (entry = W4[c*64+k][n])
__device__ __align__(16) unsigned char gW4h[8 * 5760];
__device__ __align__(16) unsigned char gW4l[8 * 5760];

__device__ __forceinline__ void split2h(float v, __half& h, __half& l) {
    h = __float2half_rn(v);
    l = __float2half_rn(v - __half2float(h));
}

__global__ void prep_kernel(const float* __restrict__ W2,
                            const float* __restrict__ W4) {
    int idx = blockIdx.x * blockDim.x + threadIdx.x;
    if (idx < 65536) {                    // W2 split: c(8) x n(64) x k(128)
        int c = idx >> 13, rem = idx & 8191;
        int n = rem >> 7, k = rem & 127;
        float v = W2[k * 512 + c * 64 + n];
        __half h, l; split2h(v, h, l);
        uint32_t off = (uint32_t)c * 17408u + (uint32_t)(n * PAD + k) * 2u;
        *(__half*)(gW2h + off) = h;
        *(__half*)(gW2l + off) = l;
    } else if (idx < 65536 + 20480) {     // W4 split: c(8) x n(40) x k(64), 2560/chunk
        int i = idx - 65536;
        int c = i / 2560, rem = i % 2560;
        int n = rem / 64, k = rem % 64;
        float v = W4[(c * 64 + k) * 40 + n];
        __half h, l; split2h(v, h, l);
        uint32_t off = (uint32_t)c * 5760u + (uint32_t)(n * HPAD + k) * 2u;
        *(__half*)(gW4h + off) = h;
        *(__half*)(gW4l + off) = l;
    }
}

// ---------------- PTX helpers ----------------
__device__ __forceinline__ uint32_t smem_u32(const void* p) {
    uint32_t a;
    asm("{ .reg .u64 t; cvta.to.shared.u64 t, %1; cvt.u32.u64 %0, t; }"
        : "=r"(a) : "l"(p));
    return a;
}
__device__ __forceinline__ void ldsm_x4(uint32_t* r, uint32_t addr) {
    asm volatile("ldmatrix.sync.aligned.m8n8.x4.shared.b16 {%0,%1,%2,%3}, [%4];"
        : "=r"(r[0]), "=r"(r[1]), "=r"(r[2]), "=r"(r[3]) : "r"(addr));
}
__device__ __forceinline__ void ldsm_x2(uint32_t* r, uint32_t addr) {
    asm volatile("ldmatrix.sync.aligned.m8n8.x2.shared.b16 {%0,%1}, [%2];"
        : "=r"(r[0]), "=r"(r[1]) : "r"(addr));
}
__device__ __forceinline__ void mma16816(float* d, const uint32_t* a, const uint32_t* b) {
    asm volatile("mma.sync.aligned.m16n8k16.row.col.f32.f16.f16.f32 "
        "{%0,%1,%2,%3}, {%4,%5,%6,%7}, {%8,%9}, {%0,%1,%2,%3};"
        : "+f"(d[0]), "+f"(d[1]), "+f"(d[2]), "+f"(d[3])
        : "r"(a[0]), "r"(a[1]), "r"(a[2]), "r"(a[3]), "r"(b[0]), "r"(b[1]));
}

// ---------------- smem layout (bytes) ----------------
#define S_A2H  0                       // h1 hi [64][PAD] f16 = 17408
#define S_B    17408                   // W2 chunk hi / h2 hi [64][HPAD] / layer1 staging (spans into S_BL)
#define S_BL   34816                   // W2 chunk lo
#define S_W4H  52224                   // W4 chunk hi [40][HPAD] = 5760
#define S_W4L  57984
#define S_BIAS 63744                   // b1(128) b2(512) b4(40) f32 = 2720
#define SMEM_BYTES 66464

__global__ __launch_bounds__(TPB, 3)
void dqn_hmma_kernel(const float* __restrict__ x,
                     const float* __restrict__ W1,
                     const float* __restrict__ b1,
                     const float* __restrict__ b2,
                     const float* __restrict__ b4,
                     float* __restrict__ out) {
    extern __shared__ char smem[];
    const uint32_t sb = smem_u32(smem);
    const int t    = threadIdx.x;
    const int wid  = t >> 5;
    const int lane = t & 31;
    const int blk  = blockIdx.x;

    float* b1s = (float*)(smem + S_BIAS);
    float* b2s = b1s + 128;
    float* b4s = b2s + 512;

    // ---------------- stage biases + layer1 inputs (staging spans S_B..S_BL) --
    {
        float* xs  = (float*)(smem + S_B);    // 64*15 = 960 f32
        float* W1p = xs + 960;                // 36*128 = 4608 f32
        const float* xg = x + (size_t)blk * (RPB * 15);
        #pragma unroll
        for (int i = 0; i < 8; i++) {
            int idx = i * TPB + t;
            if (idx < 960) xs[idx] = xg[idx];
        }
        #pragma unroll
        for (int i = 0; i < 36; i++) W1p[i * TPB + t] = W1[i * TPB + t];
        if (t < 128) b1s[t] = b1[t];
        #pragma unroll
        for (int i = 0; i < 4; i++) b2s[i * TPB + t] = b2[i * TPB + t];
        if (t < 40) b4s[t] = b4[t];
        __syncthreads();

        // ---------------- layer 1 (fp32 exact) -> fp16-hi A2 tile --------
        const int r  = t & 63;
        const int ch = t >> 6;
        const float* xr = xs + r * 15;
        float keep[11];
        #pragma unroll
        for (int k = 0; k < 11; k++) keep[k] = xr[k];
        int hh = (int)xr[11];      hh = hh < 0 ? 0 : (hh > 3 ? 3 : hh);
        int n0 = (int)xr[12] - 1;  n0 = n0 < 0 ? 0 : (n0 > 6 ? 6 : n0);
        int n1 = (int)xr[13] - 1;  n1 = n1 < 0 ? 0 : (n1 > 6 ? 6 : n1);
        int n2 = (int)xr[14] - 1;  n2 = n2 < 0 ? 0 : (n2 > 6 ? 6 : n2);
        const float* hrow = W1p + (11 + hh) * 128;
        const float* g0   = W1p + (15 + n0) * 128;
        const float* g1   = W1p + (22 + n1) * 128;
        const float* g2   = W1p + (29 + n2) * 128;

        __half hloc[64];
        #pragma unroll
        for (int c4 = 0; c4 < 16; c4++) {
            const int c = ch * 64 + c4 * 4;
            float4 acc = *(const float4*)(b1s + c);
            #pragma unroll
            for (int k = 0; k < 11; k++) {
                float4 w = *(const float4*)(W1p + k * 128 + c);
                acc.x += keep[k] * w.x; acc.y += keep[k] * w.y;
                acc.z += keep[k] * w.z; acc.w += keep[k] * w.w;
            }
            float4 wh = *(const float4*)(hrow + c);
            float4 w0 = *(const float4*)(g0 + c);
            float4 w1 = *(const float4*)(g1 + c);
            float4 w2 = *(const float4*)(g2 + c);
            hloc[c4 * 4 + 0] = __float2half_rn(fmaxf(acc.x + wh.x + w0.x + w1.x + w2.x, 0.f));
            hloc[c4 * 4 + 1] = __float2half_rn(fmaxf(acc.y + wh.y + w0.y + w1.y + w2.y, 0.f));
            hloc[c4 * 4 + 2] = __float2half_rn(fmaxf(acc.z + wh.z + w0.z + w1.z + w2.z, 0.f));
            hloc[c4 * 4 + 3] = __float2half_rn(fmaxf(acc.w + wh.w + w0.w + w1.w + w2.w, 0.f));
        }
        __syncthreads();   // staging region free before A2 writes? A2 is separate region; but
                           // wait for all reads of xs/W1p before chunk loop reuses S_B.
        #pragma unroll
        for (int c4 = 0; c4 < 16; c4++) {
            const int c = ch * 64 + c4 * 4;
            uint32_t off = (uint32_t)((t & 63) * PAD + c) * 2u;
            *(__half2*)(smem + S_A2H + off)     = __halves2half2(hloc[c4 * 4], hloc[c4 * 4 + 1]);
            *(__half2*)(smem + S_A2H + off + 4) = __halves2half2(hloc[c4 * 4 + 2], hloc[c4 * 4 + 3]);
        }
    }
    __syncthreads();

    // ---------------- fragment lane mappings ----------------
    const int lr  = lane & 15;                       // ldmatrix A row
    const int lc  = (lane >> 4) << 3;                // ldmatrix A col
    const int bn2 = (lane & 7) | ((lane >> 4) << 3); // B x4: row within 16
    const int bk2 = lane & 8;                        // B x4: k offset 0/8
    const int br  = lane & 7;                        // B x2 row
    const int bc  = ((lane >> 3) & 1) << 3;          // B x2 col
    const int gid = lane >> 2;
    const int tig = lane & 3;

    const int mi  = wid & 1;               // layer2 M32 block
    const int ni  = wid >> 1;              // layer2 N32 block
    const int mi3 = wid & 1;               // layer3 M32 block
    const int kh3 = wid >> 1;              // layer3 K32 half

    float o3[2][5][4];
    #pragma unroll
    for (int a = 0; a < 2; a++)
        #pragma unroll
        for (int b = 0; b < 5; b++)
            #pragma unroll
            for (int d = 0; d < 4; d++) o3[a][b][d] = 0.f;

    // ---------------- chunk loop: 8 x 64 j-cols ----------------
    for (int c = 0; c < 8; c++) {
        // copy W2 chunk (hi+lo) + W4 chunk (hi+lo)
        {
            const uint4* s1 = (const uint4*)(gW2h + (size_t)c * 17408);
            const uint4* s2 = (const uint4*)(gW2l + (size_t)c * 17408);
            uint4* d1 = (uint4*)(smem + S_B);
            uint4* d2 = (uint4*)(smem + S_BL);
            #pragma unroll
            for (int i = 0; i < 9; i++) {
                int idx = i * TPB + t;
                if (idx < 1088) { d1[idx] = s1[idx]; d2[idx] = s2[idx]; }
            }
            const uint4* s3 = (const uint4*)(gW4h + (size_t)c * 5760);
            const uint4* s4 = (const uint4*)(gW4l + (size_t)c * 5760);
            uint4* d3 = (uint4*)(smem + S_W4H);
            uint4* d4 = (uint4*)(smem + S_W4L);
            #pragma unroll
            for (int i = 0; i < 3; i++) {
                int idx = i * TPB + t;
                if (idx < 360) { d3[idx] = s3[idx]; d4[idx] = s4[idx]; }
            }
        }
        __syncthreads();

        // ---- layer2: warp 32x32 tile, K=128, 2-term split (A hi only) ----
        float acc[2][4][4];
        #pragma unroll
        for (int a = 0; a < 2; a++)
            #pragma unroll
            for (int b = 0; b < 4; b++)
                #pragma unroll
                for (int d = 0; d < 4; d++) acc[a][b][d] = 0.f;

        #pragma unroll
        for (int kt = 0; kt < 8; kt++) {
            const int k0 = kt * 16;
            uint32_t ah[2][4];
            #pragma unroll
            for (int mt = 0; mt < 2; mt++) {
                int row0 = mi * 32 + mt * 16;
                uint32_t off = (uint32_t)((row0 + lr) * PAD + k0 + lc) * 2u;
                ldsm_x4(ah[mt], sb + S_A2H + off);
            }
            uint32_t bh[4][2], bl[4][2];
            #pragma unroll
            for (int p = 0; p < 2; p++) {   // nt pairs (0,1),(2,3) via x4
                int nrow0 = ni * 32 + p * 16;
                uint32_t off = (uint32_t)((nrow0 + bn2) * PAD + k0 + bk2) * 2u;
                uint32_t tmp[4];
                ldsm_x4(tmp, sb + S_B + off);
                bh[2*p][0] = tmp[0]; bh[2*p][1] = tmp[1];
                bh[2*p+1][0] = tmp[2]; bh[2*p+1][1] = tmp[3];
                ldsm_x4(tmp, sb + S_BL + off);
                bl[2*p][0] = tmp[0]; bl[2*p][1] = tmp[1];
                bl[2*p+1][0] = tmp[2]; bl[2*p+1][1] = tmp[3];
            }
            #pragma unroll
            for (int mt = 0; mt < 2; mt++)
                #pragma unroll
                for (int nt = 0; nt < 4; nt++) {
                    mma16816(acc[mt][nt], ah[mt], bh[nt]);
                    mma16816(acc[mt][nt], ah[mt], bl[nt]);
                }
        }
        __syncthreads();   // all warps done reading W2 chunk

        // ---- epilogue: +b2, relu, fp16-hi -> h2 tile (aliases W2-hi buf) ----
        #pragma unroll
        for (int mt = 0; mt < 2; mt++)
            #pragma unroll
            for (int nt = 0; nt < 4; nt++) {
                int j = ni * 32 + nt * 8 + 2 * tig;
                float bj0 = b2s[c * 64 + j], bj1 = b2s[c * 64 + j + 1];
                int row0 = mi * 32 + mt * 16 + gid;
                int row1 = row0 + 8;
                __half h0 = __float2half_rn(fmaxf(acc[mt][nt][0] + bj0, 0.f));
                __half h1 = __float2half_rn(fmaxf(acc[mt][nt][1] + bj1, 0.f));
                __half h2v = __float2half_rn(fmaxf(acc[mt][nt][2] + bj0, 0.f));
                __half h3 = __float2half_rn(fmaxf(acc[mt][nt][3] + bj1, 0.f));
                *(__half2*)(smem + S_B + (uint32_t)(row0 * HPAD + j) * 2u) = __halves2half2(h0, h1);
                *(__half2*)(smem + S_B + (uint32_t)(row1 * HPAD + j) * 2u) = __halves2half2(h2v, h3);
            }
        __syncthreads();

        // ---- layer3 partial: h2 chunk (K=64) x W4 chunk, K split 2-way ----
        #pragma unroll
        for (int kt = 0; kt < 2; kt++) {
            const int k0 = kh3 * 32 + kt * 16;
            uint32_t ah[2][4];
            #pragma unroll
            for (int mt = 0; mt < 2; mt++) {
                int row0 = mi3 * 32 + mt * 16;
                uint32_t off = (uint32_t)((row0 + lr) * HPAD + k0 + lc) * 2u;
                ldsm_x4(ah[mt], sb + S_B + off);
            }
            uint32_t bh[5][2], bl[5][2];
            #pragma unroll
            for (int p = 0; p < 2; p++) {   // n pairs (0,1),(2,3) via x4
                uint32_t off = (uint32_t)((p * 16 + bn2) * HPAD + k0 + bk2) * 2u;
                uint32_t tmp[4];
                ldsm_x4(tmp, sb + S_W4H + off);
                bh[2*p][0] = tmp[0]; bh[2*p][1] = tmp[1];
                bh[2*p+1][0] = tmp[2]; bh[2*p+1][1] = tmp[3];
                ldsm_x4(tmp, sb + S_W4L + off);
                bl[2*p][0] = tmp[0]; bl[2*p][1] = tmp[1];
                bl[2*p+1][0] = tmp[2]; bl[2*p+1][1] = tmp[3];
            }
            {   // n group 4 (rows 32-39) via x2
                uint32_t off = (uint32_t)((32 + br) * HPAD + k0 + bc) * 2u;
                ldsm_x2(bh[4], sb + S_W4H + off);
                ldsm_x2(bl[4], sb + S_W4L + off);
            }
            #pragma unroll
            for (int mt = 0; mt < 2; mt++)
                #pragma unroll
                for (int nt = 0; nt < 5; nt++) {
                    mma16816(o3[mt][nt], ah[mt], bh[nt]);
                    mma16816(o3[mt][nt], ah[mt], bl[nt]);
                }
        }
        __syncthreads();   // h2/W4 reads done before next chunk copy
    }

    // ---------------- cross-warp K reduction + output ----------------
    float* sred = (float*)smem;   // reuse A2 region: 64*40 f32 = 10240B
    if (kh3 == 1) {
        #pragma unroll
        for (int mt = 0; mt < 2; mt++)
            #pragma unroll
            for (int nt = 0; nt < 5; nt++) {
                int j = nt * 8 + 2 * tig;
                int r0 = mi3 * 32 + mt * 16 + gid;
                int r1 = r0 + 8;
                sred[r0 * 40 + j]     = o3[mt][nt][0];
                sred[r0 * 40 + j + 1] = o3[mt][nt][1];
                sred[r1 * 40 + j]     = o3[mt][nt][2];
                sred[r1 * 40 + j + 1] = o3[mt][nt][3];
            }
    }
    __syncthreads();
    if (kh3 == 0) {
        #pragma unroll
        for (int mt = 0; mt < 2; mt++)
            #pragma unroll
            for (int nt = 0; nt < 5; nt++) {
                int j = nt * 8 + 2 * tig;
                int r0 = mi3 * 32 + mt * 16 + gid;
                int r1 = r0 + 8;
                float s0 = o3[mt][nt][0] + sred[r0 * 40 + j]     + b4s[j];
                float s1 = o3[mt][nt][1] + sred[r0 * 40 + j + 1] + b4s[j + 1];
                float s2 = o3[mt][nt][2] + sred[r1 * 40 + j]     + b4s[j];
                float s3 = o3[mt][nt][3] + sred[r1 * 40 + j + 1] + b4s[j + 1];
                *(float2*)(out + ((size_t)blk * RPB + r0) * 40 + j) = make_float2(s0, s1);
                *(float2*)(out + ((size_t)blk * RPB + r1) * 40 + j) = make_float2(s2, s3);
            }
    }
}

extern "C" void kernel_launch(void* const* d_in, const int* in_sizes, int n_in,
                              void* d_out, int out_size) {
    const float* x  = (const float*)d_in[0];
    const float* W1 = (const float*)d_in[1];
    const float* b1 = (const float*)d_in[2];
    const float* W2 = (const float*)d_in[3];
    const float* b2 = (const float*)d_in[4];
    const float* W4 = (const float*)d_in[5];
    const float* b4 = (const float*)d_in[6];
    float* out = (float*)d_out;

    prep_kernel<<<336, 256>>>(W2, W4);

    const int B = in_sizes[0] / 15;      // 131072
    const int grid = B / RPB;            // 2048
    cudaFuncSetAttribute(dqn_hmma_kernel,
                         cudaFuncAttributeMaxDynamicSharedMemorySize, SMEM_BYTES);
    dqn_hmma_kernel<<<grid, TPB, SMEM_BYTES>>>(x, W1, b1, b2, b4, out);
}

// round 9
// speedup vs baseline: 1.7870x; 1.3276x over previous
#include <cuda_runtime.h>
#include <cuda_fp16.h>
#include <cstdint>

#define TPB 128
#define RPB 64
#define PAD 136    // fp16 elems per k-row of A2 tile (272B stride, conflict-free)
#define HPAD 72    // fp16 elems per row of h2 tile (144B stride, conflict-free)

// ---------------- fragment-ordered split-fp16 weights in device globals ----
// W2: 512 fragments (c8 x ni2 x kt8 x nt4), each 32 lanes x uint4{hi0,hi1,lo0,lo1}
__device__ __align__(16) uint4 gW2f[16384];
// W4: 160 fragments (c8 x kh2 x kt2 x nt5)
__device__ __align__(16) uint4 gW4f[5120];

__device__ __forceinline__ void split_pack(float a, float b, uint32_t& hi, uint32_t& lo) {
    __half ha = __float2half_rn(a), hb = __float2half_rn(b);
    __half la = __float2half_rn(a - __half2float(ha));
    __half lb = __float2half_rn(b - __half2float(hb));
    __half2 ph = __halves2half2(ha, hb), pl = __halves2half2(la, lb);
    hi = *(uint32_t*)&ph;
    lo = *(uint32_t*)&pl;
}

__global__ void prep_kernel(const float* __restrict__ W2,
                            const float* __restrict__ W4) {
    int idx = blockIdx.x * blockDim.x + threadIdx.x;
    if (idx < 16384) {
        // W2 fragment: fid = c*64 + ni*32 + kt*4 + nt
        int lane = idx & 31, fid = idx >> 5;
        int nt = fid & 3, kt = (fid >> 2) & 7, ni = (fid >> 5) & 1, c = fid >> 6;
        int n  = c * 64 + ni * 32 + nt * 8 + (lane >> 2);
        int k0 = kt * 16 + (lane & 3) * 2;
        uint32_t h0, l0, h1, l1;
        split_pack(W2[k0 * 512 + n],       W2[(k0 + 1) * 512 + n], h0, l0);
        split_pack(W2[(k0 + 8) * 512 + n], W2[(k0 + 9) * 512 + n], h1, l1);
        gW2f[idx] = make_uint4(h0, h1, l0, l1);
    } else if (idx < 16384 + 5120) {
        // W4 fragment: fid = ((c*2+kh)*2+kt)*5 + nt
        int i = idx - 16384;
        int lane = i & 31, fid = i >> 5;
        int nt = fid % 5, r = fid / 5;
        int kt = r & 1, kh = (r >> 1) & 1, c = r >> 2;
        int n = nt * 8 + (lane >> 2);
        int k = c * 64 + kh * 32 + kt * 16 + (lane & 3) * 2;
        uint32_t h0, l0, h1, l1;
        split_pack(W4[k * 40 + n],       W4[(k + 1) * 40 + n], h0, l0);
        split_pack(W4[(k + 8) * 40 + n], W4[(k + 9) * 40 + n], h1, l1);
        gW4f[i] = make_uint4(h0, h1, l0, l1);
    }
}

// ---------------- PTX helpers ----------------
__device__ __forceinline__ uint32_t smem_u32(const void* p) {
    uint32_t a;
    asm("{ .reg .u64 t; cvta.to.shared.u64 t, %1; cvt.u32.u64 %0, t; }"
        : "=r"(a) : "l"(p));
    return a;
}
__device__ __forceinline__ void ldsm_x4(uint32_t* r, uint32_t addr) {
    asm volatile("ldmatrix.sync.aligned.m8n8.x4.shared.b16 {%0,%1,%2,%3}, [%4];"
        : "=r"(r[0]), "=r"(r[1]), "=r"(r[2]), "=r"(r[3]) : "r"(addr));
}
__device__ __forceinline__ void mma16816(float* d, const uint32_t* a,
                                         uint32_t b0, uint32_t b1) {
    asm volatile("mma.sync.aligned.m16n8k16.row.col.f32.f16.f16.f32 "
        "{%0,%1,%2,%3}, {%4,%5,%6,%7}, {%8,%9}, {%0,%1,%2,%3};"
        : "+f"(d[0]), "+f"(d[1]), "+f"(d[2]), "+f"(d[3])
        : "r"(a[0]), "r"(a[1]), "r"(a[2]), "r"(a[3]), "r"(b0), "r"(b1));
}

// ---------------- smem layout (bytes) ----------------
#define S_A2H   0          // h1 hi [64][PAD] f16 = 17408; later h2 tile [64][HPAD] (9216) / sred (10240)
#define S_STAGE 17408      // layer1 staging: xs 3840 + W1p 18432 = 22272
#define S_BIAS  39680      // b1(128) b2(512) b4(40) f32 = 2720
#define SMEM_BYTES 42400

__global__ __launch_bounds__(TPB, 3)
void dqn_hmma_kernel(const float* __restrict__ x,
                     const float* __restrict__ W1,
                     const float* __restrict__ b1,
                     const float* __restrict__ b2,
                     const float* __restrict__ b4,
                     float* __restrict__ out) {
    extern __shared__ char smem[];
    const uint32_t sb = smem_u32(smem);
    const int t    = threadIdx.x;
    const int wid  = t >> 5;
    const int lane = t & 31;
    const int blk  = blockIdx.x;

    float* b1s = (float*)(smem + S_BIAS);
    float* b2s = b1s + 128;
    float* b4s = b2s + 512;

    // ---------------- stage biases + layer1 inputs ----------------
    {
        float* xs  = (float*)(smem + S_STAGE);   // 64*15 = 960 f32
        float* W1p = xs + 960;                   // 36*128 = 4608 f32
        const float* xg = x + (size_t)blk * (RPB * 15);
        #pragma unroll
        for (int i = 0; i < 8; i++) {
            int idx = i * TPB + t;
            if (idx < 960) xs[idx] = xg[idx];
        }
        #pragma unroll
        for (int i = 0; i < 36; i++) W1p[i * TPB + t] = W1[i * TPB + t];
        if (t < 128) b1s[t] = b1[t];
        #pragma unroll
        for (int i = 0; i < 4; i++) b2s[i * TPB + t] = b2[i * TPB + t];
        if (t < 40) b4s[t] = b4[t];
        __syncthreads();

        // ---------------- layer 1 (fp32 exact) -> fp16-hi A2 tile --------
        const int r  = t & 63;
        const int ch = t >> 6;
        const float* xr = xs + r * 15;
        float keep[11];
        #pragma unroll
        for (int k = 0; k < 11; k++) keep[k] = xr[k];
        int hh = (int)xr[11];      hh = hh < 0 ? 0 : (hh > 3 ? 3 : hh);
        int n0 = (int)xr[12] - 1;  n0 = n0 < 0 ? 0 : (n0 > 6 ? 6 : n0);
        int n1 = (int)xr[13] - 1;  n1 = n1 < 0 ? 0 : (n1 > 6 ? 6 : n1);
        int n2 = (int)xr[14] - 1;  n2 = n2 < 0 ? 0 : (n2 > 6 ? 6 : n2);
        const float* hrow = W1p + (11 + hh) * 128;
        const float* g0   = W1p + (15 + n0) * 128;
        const float* g1   = W1p + (22 + n1) * 128;
        const float* g2   = W1p + (29 + n2) * 128;

        #pragma unroll
        for (int c4 = 0; c4 < 16; c4++) {
            const int c = ch * 64 + c4 * 4;
            float4 acc = *(const float4*)(b1s + c);
            #pragma unroll
            for (int k = 0; k < 11; k++) {
                float4 w = *(const float4*)(W1p + k * 128 + c);
                acc.x += keep[k] * w.x; acc.y += keep[k] * w.y;
                acc.z += keep[k] * w.z; acc.w += keep[k] * w.w;
            }
            float4 wh = *(const float4*)(hrow + c);
            float4 w0 = *(const float4*)(g0 + c);
            float4 w1 = *(const float4*)(g1 + c);
            float4 w2 = *(const float4*)(g2 + c);
            __half h0v = __float2half_rn(fmaxf(acc.x + wh.x + w0.x + w1.x + w2.x, 0.f));
            __half h1v = __float2half_rn(fmaxf(acc.y + wh.y + w0.y + w1.y + w2.y, 0.f));
            __half h2v = __float2half_rn(fmaxf(acc.z + wh.z + w0.z + w1.z + w2.z, 0.f));
            __half h3v = __float2half_rn(fmaxf(acc.w + wh.w + w0.w + w1.w + w2.w, 0.f));
            uint32_t off = (uint32_t)(r * PAD + c) * 2u;
            *(__half2*)(smem + S_A2H + off)     = __halves2half2(h0v, h1v);
            *(__half2*)(smem + S_A2H + off + 4) = __halves2half2(h2v, h3v);
        }
    }
    __syncthreads();

    // ---------------- fragment lane mappings ----------------
    const int lr  = lane & 15;               // ldmatrix A row
    const int lc  = (lane >> 4) << 3;        // ldmatrix A col
    const int gid = lane >> 2;
    const int tig = lane & 3;

    const int mi  = wid & 1;                 // layer2 M32 block
    const int ni  = wid >> 1;                // layer2 N32 block
    const int mi3 = wid & 1;                 // layer3 M32 block
    const int kh3 = wid >> 1;                // layer3 K32 half

    // ---- preload register-resident A fragments (h1-hi, 32x128 per warp) ----
    uint32_t a2f[2][8][4];
    #pragma unroll
    for (int kt = 0; kt < 8; kt++)
        #pragma unroll
        for (int mt = 0; mt < 2; mt++) {
            uint32_t off = (uint32_t)((mi * 32 + mt * 16 + lr) * PAD + kt * 16 + lc) * 2u;
            ldsm_x4(a2f[mt][kt], sb + S_A2H + off);
        }
    __syncthreads();   // A2 region now reusable as h2 tile

    float o3[2][5][4];
    #pragma unroll
    for (int a = 0; a < 2; a++)
        #pragma unroll
        for (int b = 0; b < 5; b++)
            #pragma unroll
            for (int d = 0; d < 4; d++) o3[a][b][d] = 0.f;

    // ---------------- chunk loop: 8 x 64 j-cols ----------------
    for (int c = 0; c < 8; c++) {
        // ---- layer2: warp 32x32 tile, K=128, B fragments direct from gmem ----
        float acc[2][4][4];
        #pragma unroll
        for (int a = 0; a < 2; a++)
            #pragma unroll
            for (int b = 0; b < 4; b++)
                #pragma unroll
                for (int d = 0; d < 4; d++) acc[a][b][d] = 0.f;

        const uint4* w2base = gW2f + ((size_t)(c * 2 + ni) << 10) + lane;  // 32 frags * 32
        #pragma unroll
        for (int kt = 0; kt < 8; kt++) {
            uint4 w[4];
            #pragma unroll
            for (int nt = 0; nt < 4; nt++)
                w[nt] = __ldg(w2base + (kt * 4 + nt) * 32);
            #pragma unroll
            for (int mt = 0; mt < 2; mt++)
                #pragma unroll
                for (int nt = 0; nt < 4; nt++) {
                    mma16816(acc[mt][nt], a2f[mt][kt], w[nt].x, w[nt].y);
                    mma16816(acc[mt][nt], a2f[mt][kt], w[nt].z, w[nt].w);
                }
        }

        // ---- epilogue: +b2, relu, fp16-hi -> h2 tile (aliases A2 region) ----
        #pragma unroll
        for (int mt = 0; mt < 2; mt++)
            #pragma unroll
            for (int nt = 0; nt < 4; nt++) {
                int j = ni * 32 + nt * 8 + 2 * tig;
                float bj0 = b2s[c * 64 + j], bj1 = b2s[c * 64 + j + 1];
                int row0 = mi * 32 + mt * 16 + gid;
                int row1 = row0 + 8;
                __half h0 = __float2half_rn(fmaxf(acc[mt][nt][0] + bj0, 0.f));
                __half h1 = __float2half_rn(fmaxf(acc[mt][nt][1] + bj1, 0.f));
                __half h2v = __float2half_rn(fmaxf(acc[mt][nt][2] + bj0, 0.f));
                __half h3 = __float2half_rn(fmaxf(acc[mt][nt][3] + bj1, 0.f));
                *(__half2*)(smem + S_A2H + (uint32_t)(row0 * HPAD + j) * 2u) = __halves2half2(h0, h1);
                *(__half2*)(smem + S_A2H + (uint32_t)(row1 * HPAD + j) * 2u) = __halves2half2(h2v, h3);
            }
        __syncthreads();

        // ---- layer3 partial: h2 (K=64, split 2-way) x W4 fragments ----
        #pragma unroll
        for (int kt = 0; kt < 2; kt++) {
            uint32_t ah[2][4];
            #pragma unroll
            for (int mt = 0; mt < 2; mt++) {
                uint32_t off = (uint32_t)((mi3 * 32 + mt * 16 + lr) * HPAD
                                          + kh3 * 32 + kt * 16 + lc) * 2u;
                ldsm_x4(ah[mt], sb + S_A2H + off);
            }
            const uint4* w4base = gW4f + (size_t)(((c * 2 + kh3) * 2 + kt) * 5) * 32 + lane;
            uint4 w[5];
            #pragma unroll
            for (int nt = 0; nt < 5; nt++) w[nt] = __ldg(w4base + nt * 32);
            #pragma unroll
            for (int mt = 0; mt < 2; mt++)
                #pragma unroll
                for (int nt = 0; nt < 5; nt++) {
                    mma16816(o3[mt][nt], ah[mt], w[nt].x, w[nt].y);
                    mma16816(o3[mt][nt], ah[mt], w[nt].z, w[nt].w);
                }
        }
        __syncthreads();   // h2 reads done before next chunk's epilogue overwrites
    }

    // ---------------- cross-warp K reduction + output ----------------
    float* sred = (float*)smem;   // aliases h2 region: 64*40 f32 = 10240B
    if (kh3 == 1) {
        #pragma unroll
        for (int mt = 0; mt < 2; mt++)
            #pragma unroll
            for (int nt = 0; nt < 5; nt++) {
                int j = nt * 8 + 2 * tig;
                int r0 = mi3 * 32 + mt * 16 + gid;
                int r1 = r0 + 8;
                sred[r0 * 40 + j]     = o3[mt][nt][0];
                sred[r0 * 40 + j + 1] = o3[mt][nt][1];
                sred[r1 * 40 + j]     = o3[mt][nt][2];
                sred[r1 * 40 + j + 1] = o3[mt][nt][3];
            }
    }
    __syncthreads();
    if (kh3 == 0) {
        #pragma unroll
        for (int mt = 0; mt < 2; mt++)
            #pragma unroll
            for (int nt = 0; nt < 5; nt++) {
                int j = nt * 8 + 2 * tig;
                int r0 = mi3 * 32 + mt * 16 + gid;
                int r1 = r0 + 8;
                float s0 = o3[mt][nt][0] + sred[r0 * 40 + j]     + b4s[j];
                float s1 = o3[mt][nt][1] + sred[r0 * 40 + j + 1] + b4s[j + 1];
                float s2 = o3[mt][nt][2] + sred[r1 * 40 + j]     + b4s[j];
                float s3 = o3[mt][nt][3] + sred[r1 * 40 + j + 1] + b4s[j + 1];
                *(float2*)(out + ((size_t)blk * RPB + r0) * 40 + j) = make_float2(s0, s1);
                *(float2*)(out + ((size_t)blk * RPB + r1) * 40 + j) = make_float2(s2, s3);
            }
    }
}

extern "C" void kernel_launch(void* const* d_in, const int* in_sizes, int n_in,
                              void* d_out, int out_size) {
    const float* x  = (const float*)d_in[0];
    const float* W1 = (const float*)d_in[1];
    const float* b1 = (const float*)d_in[2];
    const float* W2 = (const float*)d_in[3];
    const float* b2 = (const float*)d_in[4];
    const float* W4 = (const float*)d_in[5];
    const float* b4 = (const float*)d_in[6];
    float* out = (float*)d_out;

    prep_kernel<<<84, 256>>>(W2, W4);

    const int B = in_sizes[0] / 15;      // 131072
    const int grid = B / RPB;            // 2048
    cudaFuncSetAttribute(dqn_hmma_kernel,
                         cudaFuncAttributeMaxDynamicSharedMemorySize, SMEM_BYTES);
    dqn_hmma_kernel<<<grid, TPB, SMEM_BYTES>>>(x, W1, b1, b2, b4, out);
}

// round 10
// speedup vs baseline: 1.8863x; 1.0556x over previous
#include <cuda_runtime.h>
#include <cuda_fp16.h>
#include <cstdint>

#define TPB 128
#define RPB 64
#define PAD 136    // fp16 elems per k-row of A2 tile (272B stride, conflict-free)

// ---------------- fragment-ordered split-fp16 weights in device globals ----
// W2: 512 fragments (c8 x ni2 x kt8 x nt4), each 32 lanes x uint4{hi0,hi1,lo0,lo1}
__device__ __align__(16) uint4 gW2f[16384];
// W4: 160 fragments (c8 x ni2 x kt2 x nt5)
__device__ __align__(16) uint4 gW4f[5120];

__device__ __forceinline__ void split_pack(float a, float b, uint32_t& hi, uint32_t& lo) {
    __half ha = __float2half_rn(a), hb = __float2half_rn(b);
    __half la = __float2half_rn(a - __half2float(ha));
    __half lb = __float2half_rn(b - __half2float(hb));
    __half2 ph = __halves2half2(ha, hb), pl = __halves2half2(la, lb);
    hi = *(uint32_t*)&ph;
    lo = *(uint32_t*)&pl;
}

__global__ void prep_kernel(const float* __restrict__ W2,
                            const float* __restrict__ W4) {
    int idx = blockIdx.x * blockDim.x + threadIdx.x;
    if (idx < 16384) {
        // W2 fragment: fid = c*64 + ni*32 + kt*4 + nt
        int lane = idx & 31, fid = idx >> 5;
        int nt = fid & 3, kt = (fid >> 2) & 7, ni = (fid >> 5) & 1, c = fid >> 6;
        int n  = c * 64 + ni * 32 + nt * 8 + (lane >> 2);
        int k0 = kt * 16 + (lane & 3) * 2;
        uint32_t h0, l0, h1, l1;
        split_pack(W2[k0 * 512 + n],       W2[(k0 + 1) * 512 + n], h0, l0);
        split_pack(W2[(k0 + 8) * 512 + n], W2[(k0 + 9) * 512 + n], h1, l1);
        gW2f[idx] = make_uint4(h0, h1, l0, l1);
    } else if (idx < 16384 + 5120) {
        // W4 fragment: fid = ((c*2+ni)*2+kt)*5 + nt ; K3 = j = c*64 + ni*32 + kt*16
        int i = idx - 16384;
        int lane = i & 31, fid = i >> 5;
        int nt = fid % 5, r = fid / 5;
        int kt = r & 1, ni = (r >> 1) & 1, c = r >> 2;
        int n = nt * 8 + (lane >> 2);
        int k = c * 64 + ni * 32 + kt * 16 + (lane & 3) * 2;
        uint32_t h0, l0, h1, l1;
        split_pack(W4[k * 40 + n],       W4[(k + 1) * 40 + n], h0, l0);
        split_pack(W4[(k + 8) * 40 + n], W4[(k + 9) * 40 + n], h1, l1);
        gW4f[i] = make_uint4(h0, h1, l0, l1);
    }
}

// ---------------- PTX helpers ----------------
__device__ __forceinline__ uint32_t smem_u32(const void* p) {
    uint32_t a;
    asm("{ .reg .u64 t; cvta.to.shared.u64 t, %1; cvt.u32.u64 %0, t; }"
        : "=r"(a) : "l"(p));
    return a;
}
__device__ __forceinline__ void ldsm_x4(uint32_t* r, uint32_t addr) {
    asm volatile("ldmatrix.sync.aligned.m8n8.x4.shared.b16 {%0,%1,%2,%3}, [%4];"
        : "=r"(r[0]), "=r"(r[1]), "=r"(r[2]), "=r"(r[3]) : "r"(addr));
}
__device__ __forceinline__ void mma16816(float* d, const uint32_t* a,
                                         uint32_t b0, uint32_t b1) {
    asm volatile("mma.sync.aligned.m16n8k16.row.col.f32.f16.f16.f32 "
        "{%0,%1,%2,%3}, {%4,%5,%6,%7}, {%8,%9}, {%0,%1,%2,%3};"
        : "+f"(d[0]), "+f"(d[1]), "+f"(d[2]), "+f"(d[3])
        : "r"(a[0]), "r"(a[1]), "r"(a[2]), "r"(a[3]), "r"(b0), "r"(b1));
}
__device__ __forceinline__ uint32_t pack_relu_h2(float v0, float v1, float b0, float b1) {
    __half2 p = __floats2half2_rn(fmaxf(v0 + b0, 0.f), fmaxf(v1 + b1, 0.f));
    return *(uint32_t*)&p;
}

// ---------------- smem layout (bytes) ----------------
#define S_A2H   0          // h1 hi [64][PAD] f16 = 17408 ; later sred 10240
#define S_STAGE 17408      // layer1 staging: xs 3840 + W1p 18432
#define S_BIAS  39680      // b1(128) b2(512) b4(40) f32 = 2720
#define SMEM_BYTES 42400

__global__ __launch_bounds__(TPB, 3)
void dqn_hmma_kernel(const float* __restrict__ x,
                     const float* __restrict__ W1,
                     const float* __restrict__ b1,
                     const float* __restrict__ b2,
                     const float* __restrict__ b4,
                     float* __restrict__ out) {
    extern __shared__ char smem[];
    const uint32_t sb = smem_u32(smem);
    const int t    = threadIdx.x;
    const int wid  = t >> 5;
    const int lane = t & 31;
    const int blk  = blockIdx.x;

    float* b1s = (float*)(smem + S_BIAS);
    float* b2s = b1s + 128;
    float* b4s = b2s + 512;

    // ---------------- stage biases + layer1 inputs ----------------
    {
        float* xs  = (float*)(smem + S_STAGE);
        float* W1p = xs + 960;
        const float* xg = x + (size_t)blk * (RPB * 15);
        #pragma unroll
        for (int i = 0; i < 8; i++) {
            int idx = i * TPB + t;
            if (idx < 960) xs[idx] = xg[idx];
        }
        #pragma unroll
        for (int i = 0; i < 36; i++) W1p[i * TPB + t] = W1[i * TPB + t];
        if (t < 128) b1s[t] = b1[t];
        #pragma unroll
        for (int i = 0; i < 4; i++) b2s[i * TPB + t] = b2[i * TPB + t];
        if (t < 40) b4s[t] = b4[t];
        __syncthreads();

        // ---------------- layer 1 (fp32 exact) -> fp16-hi A2 tile --------
        const int r  = t & 63;
        const int ch = t >> 6;
        const float* xr = xs + r * 15;
        float keep[11];
        #pragma unroll
        for (int k = 0; k < 11; k++) keep[k] = xr[k];
        int hh = (int)xr[11];      hh = hh < 0 ? 0 : (hh > 3 ? 3 : hh);
        int n0 = (int)xr[12] - 1;  n0 = n0 < 0 ? 0 : (n0 > 6 ? 6 : n0);
        int n1 = (int)xr[13] - 1;  n1 = n1 < 0 ? 0 : (n1 > 6 ? 6 : n1);
        int n2 = (int)xr[14] - 1;  n2 = n2 < 0 ? 0 : (n2 > 6 ? 6 : n2);
        const float* hrow = W1p + (11 + hh) * 128;
        const float* g0   = W1p + (15 + n0) * 128;
        const float* g1   = W1p + (22 + n1) * 128;
        const float* g2   = W1p + (29 + n2) * 128;

        #pragma unroll
        for (int c4 = 0; c4 < 16; c4++) {
            const int c = ch * 64 + c4 * 4;
            float4 acc = *(const float4*)(b1s + c);
            #pragma unroll
            for (int k = 0; k < 11; k++) {
                float4 w = *(const float4*)(W1p + k * 128 + c);
                acc.x += keep[k] * w.x; acc.y += keep[k] * w.y;
                acc.z += keep[k] * w.z; acc.w += keep[k] * w.w;
            }
            float4 wh = *(const float4*)(hrow + c);
            float4 w0 = *(const float4*)(g0 + c);
            float4 w1 = *(const float4*)(g1 + c);
            float4 w2 = *(const float4*)(g2 + c);
            __half h0v = __float2half_rn(fmaxf(acc.x + wh.x + w0.x + w1.x + w2.x, 0.f));
            __half h1v = __float2half_rn(fmaxf(acc.y + wh.y + w0.y + w1.y + w2.y, 0.f));
            __half h2v = __float2half_rn(fmaxf(acc.z + wh.z + w0.z + w1.z + w2.z, 0.f));
            __half h3v = __float2half_rn(fmaxf(acc.w + wh.w + w0.w + w1.w + w2.w, 0.f));
            uint32_t off = (uint32_t)(r * PAD + c) * 2u;
            *(__half2*)(smem + S_A2H + off)     = __halves2half2(h0v, h1v);
            *(__half2*)(smem + S_A2H + off + 4) = __halves2half2(h2v, h3v);
        }
    }
    __syncthreads();

    // ---------------- fragment lane mappings ----------------
    const int lr  = lane & 15;
    const int lc  = (lane >> 4) << 3;
    const int gid = lane >> 2;
    const int tig = lane & 3;

    const int mi = wid & 1;                 // M32 block (layers 2+3)
    const int ni = wid >> 1;                // layer2 N32 block == layer3 K32 half

    // ---- preload register-resident A fragments (h1-hi, 32x128 per warp) ----
    uint32_t a2f[2][8][4];
    #pragma unroll
    for (int kt = 0; kt < 8; kt++)
        #pragma unroll
        for (int mt = 0; mt < 2; mt++) {
            uint32_t off = (uint32_t)((mi * 32 + mt * 16 + lr) * PAD + kt * 16 + lc) * 2u;
            ldsm_x4(a2f[mt][kt], sb + S_A2H + off);
        }
    __syncthreads();   // A2 region now reusable as sred

    float o3[2][5][4];
    #pragma unroll
    for (int a = 0; a < 2; a++)
        #pragma unroll
        for (int b = 0; b < 5; b++)
            #pragma unroll
            for (int d = 0; d < 4; d++) o3[a][b][d] = 0.f;

    // ---------------- chunk loop: 8 x 64 j-cols, NO barriers ----------------
    #pragma unroll 1
    for (int c = 0; c < 8; c++) {
        // ---- layer2: warp 32x32 tile, K=128, B fragments direct from gmem ----
        float acc[2][4][4];
        #pragma unroll
        for (int a = 0; a < 2; a++)
            #pragma unroll
            for (int b = 0; b < 4; b++)
                #pragma unroll
                for (int d = 0; d < 4; d++) acc[a][b][d] = 0.f;

        const uint4* w2base = gW2f + ((size_t)(c * 2 + ni) << 10) + lane;
        #pragma unroll
        for (int kt = 0; kt < 8; kt++) {
            uint4 w[4];
            #pragma unroll
            for (int nt = 0; nt < 4; nt++)
                w[nt] = __ldg(w2base + (kt * 4 + nt) * 32);
            #pragma unroll
            for (int mt = 0; mt < 2; mt++)
                #pragma unroll
                for (int nt = 0; nt < 4; nt++) {
                    mma16816(acc[mt][nt], a2f[mt][kt], w[nt].x, w[nt].y);
                    mma16816(acc[mt][nt], a2f[mt][kt], w[nt].z, w[nt].w);
                }
        }

        // ---- epilogue in registers: D-frag -> A-frag (h2), +b2, relu, cvt ----
        // A-frag kt3 = nt>>1 : a0,a1 from even nt tile; a2,a3 from odd nt tile.
        uint32_t a3f[2][2][4];
        #pragma unroll
        for (int mt = 0; mt < 2; mt++)
            #pragma unroll
            for (int nt = 0; nt < 4; nt++) {
                int j = c * 64 + ni * 32 + nt * 8 + 2 * tig;
                float bj0 = b2s[j], bj1 = b2s[j + 1];
                uint32_t p01 = pack_relu_h2(acc[mt][nt][0], acc[mt][nt][1], bj0, bj1);
                uint32_t p23 = pack_relu_h2(acc[mt][nt][2], acc[mt][nt][3], bj0, bj1);
                a3f[mt][nt >> 1][(nt & 1) * 2]     = p01;
                a3f[mt][nt >> 1][(nt & 1) * 2 + 1] = p23;
            }

        // ---- layer3 partial: K = this warp's j-window (ni half), from regs ----
        #pragma unroll
        for (int kt = 0; kt < 2; kt++) {
            const uint4* w4base = gW4f + (size_t)(((c * 2 + ni) * 2 + kt) * 5) * 32 + lane;
            uint4 w[5];
            #pragma unroll
            for (int nt = 0; nt < 5; nt++) w[nt] = __ldg(w4base + nt * 32);
            #pragma unroll
            for (int mt = 0; mt < 2; mt++)
                #pragma unroll
                for (int nt = 0; nt < 5; nt++) {
                    mma16816(o3[mt][nt], a3f[mt][kt], w[nt].x, w[nt].y);
                    mma16816(o3[mt][nt], a3f[mt][kt], w[nt].z, w[nt].w);
                }
        }
    }

    // ---------------- cross-warp K reduction (2-way over ni) + output -------
    float* sred = (float*)smem;   // aliases A2 region: 64*40 f32 = 10240B
    if (ni == 1) {
        #pragma unroll
        for (int mt = 0; mt < 2; mt++)
            #pragma unroll
            for (int nt = 0; nt < 5; nt++) {
                int j = nt * 8 + 2 * tig;
                int r0 = mi * 32 + mt * 16 + gid;
                int r1 = r0 + 8;
                sred[r0 * 40 + j]     = o3[mt][nt][0];
                sred[r0 * 40 + j + 1] = o3[mt][nt][1];
                sred[r1 * 40 + j]     = o3[mt][nt][2];
                sred[r1 * 40 + j + 1] = o3[mt][nt][3];
            }
    }
    __syncthreads();
    if (ni == 0) {
        #pragma unroll
        for (int mt = 0; mt < 2; mt++)
            #pragma unroll
            for (int nt = 0; nt < 5; nt++) {
                int j = nt * 8 + 2 * tig;
                int r0 = mi * 32 + mt * 16 + gid;
                int r1 = r0 + 8;
                float s0 = o3[mt][nt][0] + sred[r0 * 40 + j]     + b4s[j];
                float s1 = o3[mt][nt][1] + sred[r0 * 40 + j + 1] + b4s[j + 1];
                float s2 = o3[mt][nt][2] + sred[r1 * 40 + j]     + b4s[j];
                float s3 = o3[mt][nt][3] + sred[r1 * 40 + j + 1] + b4s[j + 1];
                *(float2*)(out + ((size_t)blk * RPB + r0) * 40 + j) = make_float2(s0, s1);
                *(float2*)(out + ((size_t)blk * RPB + r1) * 40 + j) = make_float2(s2, s3);
            }
    }
}

extern "C" void kernel_launch(void* const* d_in, const int* in_sizes, int n_in,
                              void* d_out, int out_size) {
    const float* x  = (const float*)d_in[0];
    const float* W1 = (const float*)d_in[1];
    const float* b1 = (const float*)d_in[2];
    const float* W2 = (const float*)d_in[3];
    const float* b2 = (const float*)d_in[4];
    const float* W4 = (const float*)d_in[5];
    const float* b4 = (const float*)d_in[6];
    float* out = (float*)d_out;

    prep_kernel<<<84, 256>>>(W2, W4);

    const int B = in_sizes[0] / 15;      // 131072
    const int grid = B / RPB;            // 2048
    cudaFuncSetAttribute(dqn_hmma_kernel,
                         cudaFuncAttributeMaxDynamicSharedMemorySize, SMEM_BYTES);
    dqn_hmma_kernel<<<grid, TPB, SMEM_BYTES>>>(x, W1, b1, b2, b4, out);
}